// round 5
// baseline (speedup 1.0000x reference)
#include <cuda_runtime.h>
#include <float.h>

#define Q      1024
#define D      512
#define NDATA  50000
#define NPAD   50048   // 391 * 128
#define NTILES 391     // NPAD / 128

// Scratch (allocation-free rule: __device__ globals)
// Per-query per-column-tile top-10 as order-preserving packed u64 keys.
__device__ unsigned long long g_part[(size_t)Q * NTILES * 10];   // 32 MB
__device__ float g_d2[NPAD];
__device__ int   g_t_is_i64;   // 1 if targets buffer is int64, 0 if int32

__device__ __forceinline__ unsigned long long pack_key(float v, int idx) {
    unsigned int b = __float_as_uint(v);
    b = (b & 0x80000000u) ? ~b : (b | 0x80000000u);   // monotone float -> uint
    return ((unsigned long long)b << 32) | (unsigned int)idx;
}

// ---------------------------------------------------------------------------
// Kernel 0: detect targets dtype. If the buffer is int64 (values in [0,100)),
// its int32 view has every odd word == 0. Any nonzero odd word => int32.
// ---------------------------------------------------------------------------
__global__ __launch_bounds__(256) void detect_dtype_kernel(const int* __restrict__ t32) {
    __shared__ int any_nz;
    if (threadIdx.x == 0) any_nz = 0;
    __syncthreads();
    int local = 0;
    for (int i = threadIdx.x; i < NDATA; i += 256)
        local |= t32[2 * i + 1];
    if (local) atomicOr(&any_nz, 1);
    __syncthreads();
    if (threadIdx.x == 0) g_t_is_i64 = (any_nz == 0) ? 1 : 0;
}

// ---------------------------------------------------------------------------
// Kernel 1: per-row squared norms of data (one warp per row); pads with 0.
// ---------------------------------------------------------------------------
__global__ __launch_bounds__(256) void row_norms_kernel(const float* __restrict__ data) {
    int gw   = (blockIdx.x * blockDim.x + threadIdx.x) >> 5;
    int lane = threadIdx.x & 31;
    if (gw >= NPAD) return;
    if (gw >= NDATA) { if (lane == 0) g_d2[gw] = 0.f; return; }
    const float4* row = reinterpret_cast<const float4*>(data + (size_t)gw * D);
    float s = 0.f;
#pragma unroll
    for (int j = 0; j < 4; ++j) {
        float4 v = row[lane + 32 * j];
        s += v.x * v.x + v.y * v.y + v.z * v.z + v.w * v.w;
    }
#pragma unroll
    for (int off = 16; off > 0; off >>= 1) s += __shfl_down_sync(0xffffffffu, s, off);
    if (lane == 0) g_d2[gw] = s;
}

// ---------------------------------------------------------------------------
// Kernel 2: score GEMM + fused per-tile top-10 epilogue.
// score[q][j] = ||d_j||^2 - 2 * <X_q, data_j>   (ranking-equivalent to dist)
// Double-buffered smem (one sync per K-step) + register prefetch.
// ---------------------------------------------------------------------------
#define BM 128
#define BN 128
#define BK 16
#define TM 8
#define TN 8

__global__ __launch_bounds__(256) void score_gemm_topk_kernel(const float* __restrict__ X,
                                                              const float* __restrict__ data) {
    __shared__ float As[2][BK][BM + 4];
    __shared__ float Bs[2][BK][BN + 4];

    const int tid  = threadIdx.x;
    const int tx   = tid & 15;   // 16 thread cols
    const int ty   = tid >> 4;   // 16 thread rows
    const int row0 = blockIdx.y * BM;
    const int col0 = blockIdx.x * BN;

    const int vec0 = tid;
    const int vec1 = tid + 256;
    const int ar0 = vec0 >> 2, ac0 = vec0 & 3;
    const int ar1 = vec1 >> 2, ac1 = vec1 & 3;

    float4 pa0, pa1, pb0, pb1;

    auto load_tiles = [&](int k0) {
        pa0 = *reinterpret_cast<const float4*>(X + (size_t)(row0 + ar0) * D + k0 + ac0 * 4);
        pa1 = *reinterpret_cast<const float4*>(X + (size_t)(row0 + ar1) * D + k0 + ac1 * 4);
        int g0 = col0 + ar0, g1 = col0 + ar1;
        pb0 = make_float4(0.f, 0.f, 0.f, 0.f);
        pb1 = make_float4(0.f, 0.f, 0.f, 0.f);
        if (g0 < NDATA) pb0 = *reinterpret_cast<const float4*>(data + (size_t)g0 * D + k0 + ac0 * 4);
        if (g1 < NDATA) pb1 = *reinterpret_cast<const float4*>(data + (size_t)g1 * D + k0 + ac1 * 4);
    };
    auto store_tiles = [&](int b) {
        As[b][ac0 * 4 + 0][ar0] = pa0.x; As[b][ac0 * 4 + 1][ar0] = pa0.y;
        As[b][ac0 * 4 + 2][ar0] = pa0.z; As[b][ac0 * 4 + 3][ar0] = pa0.w;
        As[b][ac1 * 4 + 0][ar1] = pa1.x; As[b][ac1 * 4 + 1][ar1] = pa1.y;
        As[b][ac1 * 4 + 2][ar1] = pa1.z; As[b][ac1 * 4 + 3][ar1] = pa1.w;
        Bs[b][ac0 * 4 + 0][ar0] = pb0.x; Bs[b][ac0 * 4 + 1][ar0] = pb0.y;
        Bs[b][ac0 * 4 + 2][ar0] = pb0.z; Bs[b][ac0 * 4 + 3][ar0] = pb0.w;
        Bs[b][ac1 * 4 + 0][ar1] = pb1.x; Bs[b][ac1 * 4 + 1][ar1] = pb1.y;
        Bs[b][ac1 * 4 + 2][ar1] = pb1.z; Bs[b][ac1 * 4 + 3][ar1] = pb1.w;
    };

    float acc[TM][TN];
#pragma unroll
    for (int i = 0; i < TM; ++i)
#pragma unroll
        for (int j = 0; j < TN; ++j) acc[i][j] = 0.f;

    load_tiles(0);
    store_tiles(0);
    __syncthreads();

    int buf = 0;
    for (int k0 = 0; k0 < D; k0 += BK) {
        const bool has_next = (k0 + BK < D);
        if (has_next) load_tiles(k0 + BK);   // global prefetch overlaps compute

#pragma unroll
        for (int kk = 0; kk < BK; ++kk) {
            float a[TM], b[TN];
            *reinterpret_cast<float4*>(&a[0]) = *reinterpret_cast<const float4*>(&As[buf][kk][ty * TM]);
            *reinterpret_cast<float4*>(&a[4]) = *reinterpret_cast<const float4*>(&As[buf][kk][ty * TM + 4]);
            *reinterpret_cast<float4*>(&b[0]) = *reinterpret_cast<const float4*>(&Bs[buf][kk][tx * TN]);
            *reinterpret_cast<float4*>(&b[4]) = *reinterpret_cast<const float4*>(&Bs[buf][kk][tx * TN + 4]);
#pragma unroll
            for (int i = 0; i < TM; ++i)
#pragma unroll
                for (int j = 0; j < TN; ++j)
                    acc[i][j] = fmaf(a[i], b[j], acc[i][j]);
        }
        if (has_next) {
            store_tiles(buf ^ 1);   // other buffer: no reader conflict
            __syncthreads();
            buf ^= 1;
        }
    }

    // ---- Fused epilogue: per query row, exact top-10 of this 128-col tile ----
    float d2c[TN];
#pragma unroll
    for (int j = 0; j < TN; ++j) d2c[j] = g_d2[col0 + tx * TN + j];

#pragma unroll
    for (int i = 0; i < TM; ++i) {
        unsigned long long k[TN];
        const int colbase = col0 + tx * TN;
#pragma unroll
        for (int j = 0; j < TN; ++j) {
            float s = fmaf(-2.f, acc[i][j], d2c[j]);
            int col = colbase + j;
            k[j] = (col < NDATA) ? pack_key(s, col) : ~0ull;
        }
        unsigned long long* dst =
            g_part + ((size_t)(row0 + ty * TM + i) * NTILES + blockIdx.x) * 10;
#pragma unroll
        for (int r = 0; r < 10; ++r) {
            // local min of remaining 8
            unsigned long long m = k[0];
#pragma unroll
            for (int j = 1; j < TN; ++j) m = (k[j] < m) ? k[j] : m;
            // half-warp min (lanes 0-15 / 16-31 are independent query rows)
#pragma unroll
            for (int off = 8; off > 0; off >>= 1) {
                unsigned long long o = __shfl_xor_sync(0xffffffffu, m, off);
                m = (o < m) ? o : m;
            }
            if (tx == 0) dst[r] = m;
            // retire the winner (keys are unique: at most one lane matches)
#pragma unroll
            for (int j = 0; j < TN; ++j) k[j] = (k[j] == m) ? ~0ull : k[j];
        }
    }
}

// ---------------------------------------------------------------------------
// Kernel 3: merge 391 sorted 10-lists per query + mode. One block per query.
// ---------------------------------------------------------------------------
__global__ __launch_bounds__(256) void merge_mode_kernel(const int* __restrict__ t32,
                                                         float* __restrict__ out) {
    const int q   = blockIdx.x;
    const int tid = threadIdx.x;
    const unsigned long long* part = g_part + (size_t)q * NTILES * 10;

    unsigned long long L[10];
#pragma unroll
    for (int i = 0; i < 10; ++i) L[i] = ~0ull;

    for (int t = tid; t < NTILES; t += 256) {
        const unsigned long long* tl = part + t * 10;
#pragma unroll
        for (int s = 0; s < 10; ++s) {
            unsigned long long key = tl[s];
            if (key >= L[9]) break;           // tile list ascending -> done
            int p = 9;
            while (p > 0 && key < L[p - 1]) { L[p] = L[p - 1]; --p; }
            L[p] = key;
        }
    }

    __shared__ unsigned long long slist[256][10];
#pragma unroll
    for (int i = 0; i < 10; ++i) slist[tid][i] = L[i];
    __syncthreads();

    for (int Lv = 128; Lv >= 1; Lv >>= 1) {
        if (tid < Lv) {
            unsigned long long A[10];
#pragma unroll
            for (int i = 0; i < 10; ++i) A[i] = slist[tid][i];
            const unsigned long long* B = slist[tid + Lv];
            unsigned long long outm[10];
            int ia = 0, ib = 0;
#pragma unroll
            for (int i = 0; i < 10; ++i) {
                unsigned long long av = A[ia], bv = B[ib];
                if (av <= bv) { outm[i] = av; ++ia; }
                else          { outm[i] = bv; ++ib; }
            }
#pragma unroll
            for (int i = 0; i < 10; ++i) slist[tid][i] = outm[i];
        }
        __syncthreads();
    }

    if (tid == 0) {
        const int is64 = g_t_is_i64;
        int lab[10];
#pragma unroll
        for (int i = 0; i < 10; ++i) {
            int w = (int)(slist[0][i] & 0xffffffffu);
            lab[i] = is64 ? t32[2 * w] : t32[w];
        }
        int bestLab = 0x7fffffff, bestCnt = 0;
#pragma unroll
        for (int i = 0; i < 10; ++i) {
            int c = 0;
#pragma unroll
            for (int j2 = 0; j2 < 10; ++j2) c += (lab[j2] == lab[i]) ? 1 : 0;
            if (c > bestCnt || (c == bestCnt && lab[i] < bestLab)) { bestCnt = c; bestLab = lab[i]; }
        }
        out[q] = (float)bestLab;
    }
}

// ---------------------------------------------------------------------------
extern "C" void kernel_launch(void* const* d_in, const int* in_sizes, int n_in,
                              void* d_out, int out_size) {
    const float* X    = nullptr;
    const float* data = nullptr;
    const int*   t32  = nullptr;
    for (int i = 0; i < n_in; ++i) {
        if (in_sizes[i] == Q * D)            X    = (const float*)d_in[i];
        else if (in_sizes[i] == NDATA * D)   data = (const float*)d_in[i];
        else if (in_sizes[i] == NDATA)       t32  = (const int*)d_in[i];
    }
    float* out = (float*)d_out;
    (void)out_size;

    detect_dtype_kernel<<<1, 256>>>(t32);
    row_norms_kernel<<<(NPAD * 32 + 255) / 256, 256>>>(data);

    dim3 grid(NPAD / BN, Q / BM);   // 391 x 8
    score_gemm_topk_kernel<<<grid, 256>>>(X, data);

    merge_mode_kernel<<<Q, 256>>>(t32, out);
}

// round 7
// speedup vs baseline: 1.2572x; 1.2572x over previous
#include <cuda_runtime.h>
#include <cuda_bf16.h>
#include <float.h>

#define Q      1024
#define D      512
#define NDATA  50000
#define NPAD   50048    // 391 * 128
#define NT32   1564     // NPAD / 32

// ---------------- device scratch (allocation-free rule) ----------------
__device__ __nv_bfloat16 g_xb[(size_t)Q * D];          // 1 MB
__device__ __nv_bfloat16 g_db[(size_t)NPAD * D];       // 51 MB (pad rows = 0)
__device__ unsigned long long g_part[(size_t)Q * NT32 * 10];  // 128 MB
__device__ int   g_cand[(size_t)Q * 64];
__device__ float g_d2[NPAD];
__device__ int   g_t_is_i64;

__device__ __forceinline__ unsigned long long pack_key(float v, int idx) {
    unsigned int b = __float_as_uint(v);
    b = (b & 0x80000000u) ? ~b : (b | 0x80000000u);   // monotone float -> uint
    return ((unsigned long long)b << 32) | (unsigned int)idx;
}
__device__ __forceinline__ unsigned long long u64min(unsigned long long a, unsigned long long b) {
    return a < b ? a : b;
}

// ---------------------------------------------------------------------------
// Kernel 0: targets dtype detect (int64 little-endian -> all odd words zero)
// ---------------------------------------------------------------------------
__global__ __launch_bounds__(256) void detect_dtype_kernel(const int* __restrict__ t32) {
    __shared__ int any_nz;
    if (threadIdx.x == 0) any_nz = 0;
    __syncthreads();
    int local = 0;
    for (int i = threadIdx.x; i < NDATA; i += 256) local |= t32[2 * i + 1];
    if (local) atomicOr(&any_nz, 1);
    __syncthreads();
    if (threadIdx.x == 0) g_t_is_i64 = (any_nz == 0) ? 1 : 0;
}

// ---------------------------------------------------------------------------
// Kernel 1: per-row squared norms (fp32, exact), pad rows -> 0
// ---------------------------------------------------------------------------
__global__ __launch_bounds__(256) void row_norms_kernel(const float* __restrict__ data) {
    int gw   = (blockIdx.x * blockDim.x + threadIdx.x) >> 5;
    int lane = threadIdx.x & 31;
    if (gw >= NPAD) return;
    if (gw >= NDATA) { if (lane == 0) g_d2[gw] = 0.f; return; }
    const float4* row = reinterpret_cast<const float4*>(data + (size_t)gw * D);
    float s = 0.f;
#pragma unroll
    for (int j = 0; j < 4; ++j) {
        float4 v = row[lane + 32 * j];
        s += v.x * v.x + v.y * v.y + v.z * v.z + v.w * v.w;
    }
#pragma unroll
    for (int off = 16; off > 0; off >>= 1) s += __shfl_down_sync(0xffffffffu, s, off);
    if (lane == 0) g_d2[gw] = s;
}

// ---------------------------------------------------------------------------
// Kernel 2a/2b: fp32 -> bf16 conversion
// ---------------------------------------------------------------------------
__global__ __launch_bounds__(256) void cvt_x_kernel(const float* __restrict__ X) {
    int i4 = blockIdx.x * blockDim.x + threadIdx.x;           // float4 index
    if (i4 >= Q * D / 4) return;
    float4 v = reinterpret_cast<const float4*>(X)[i4];
    __nv_bfloat162* o = reinterpret_cast<__nv_bfloat162*>(g_xb);
    o[2 * i4]     = __floats2bfloat162_rn(v.x, v.y);
    o[2 * i4 + 1] = __floats2bfloat162_rn(v.z, v.w);
}
__global__ __launch_bounds__(256) void cvt_d_kernel(const float* __restrict__ data) {
    int i4 = blockIdx.x * blockDim.x + threadIdx.x;
    if (i4 >= NPAD * D / 4) return;
    __nv_bfloat162* o = reinterpret_cast<__nv_bfloat162*>(g_db);
    if (i4 < NDATA * D / 4) {
        float4 v = reinterpret_cast<const float4*>(data)[i4];
        o[2 * i4]     = __floats2bfloat162_rn(v.x, v.y);
        o[2 * i4 + 1] = __floats2bfloat162_rn(v.z, v.w);
    } else {
        o[2 * i4]     = __floats2bfloat162_rn(0.f, 0.f);
        o[2 * i4 + 1] = __floats2bfloat162_rn(0.f, 0.f);
    }
}

// ---------------------------------------------------------------------------
// Kernel 3: bf16 tensor-core score GEMM + fused approx top-10 per 32-col tile.
// Block 128x128, 8 warps (warp_m = wid&1 -> 64 rows, warp_n = wid>>1 -> 32 cols)
// mma.sync.m16n8k16, fp32 accum. smem rows padded to 80B (conflict-free LDSM).
// ---------------------------------------------------------------------------
__device__ __forceinline__ void ldsm_x4(unsigned* r, unsigned addr) {
    asm volatile("ldmatrix.sync.aligned.m8n8.x4.shared.b16 {%0,%1,%2,%3}, [%4];"
                 : "=r"(r[0]), "=r"(r[1]), "=r"(r[2]), "=r"(r[3]) : "r"(addr));
}
__device__ __forceinline__ void ldsm_x2(unsigned* r, unsigned addr) {
    asm volatile("ldmatrix.sync.aligned.m8n8.x2.shared.b16 {%0,%1}, [%2];"
                 : "=r"(r[0]), "=r"(r[1]) : "r"(addr));
}
__device__ __forceinline__ void mma16816(float* c, const unsigned* a, const unsigned* b) {
    asm volatile("mma.sync.aligned.m16n8k16.row.col.f32.bf16.bf16.f32 "
                 "{%0,%1,%2,%3}, {%4,%5,%6,%7}, {%8,%9}, {%0,%1,%2,%3};"
                 : "+f"(c[0]), "+f"(c[1]), "+f"(c[2]), "+f"(c[3])
                 : "r"(a[0]), "r"(a[1]), "r"(a[2]), "r"(a[3]), "r"(b[0]), "r"(b[1]));
}

#define SROW 80   // bytes per smem row (32 bf16 = 64B + 16B pad)

__global__ __launch_bounds__(256, 2) void mma_topk_kernel() {
    __shared__ __align__(16) unsigned char sA[2][128 * SROW];
    __shared__ __align__(16) unsigned char sB[2][128 * SROW];

    const int tid    = threadIdx.x;
    const int lane   = tid & 31;
    const int wid    = tid >> 5;
    const int warp_m = wid & 1;
    const int warp_n = wid >> 1;
    const int row0   = blockIdx.y * 128;
    const int col0   = blockIdx.x * 128;

    // global load coords: 2 uint4 per tensor per thread
    const int r  = tid >> 2;        // 0..63
    const int c8 = tid & 3;         // 16B chunk within 32-elem K slab

    const __nv_bfloat16* gA = g_xb + (size_t)(row0 + r) * D + c8 * 8;
    const __nv_bfloat16* gB = g_db + (size_t)(col0 + r) * D + c8 * 8;
    const size_t rowskip = (size_t)64 * D;

    uint4 pa0, pa1, pb0, pb1;
    auto gload = [&](int chunk) {
        const __nv_bfloat16* a = gA + chunk * 32;
        const __nv_bfloat16* b = gB + chunk * 32;
        pa0 = *reinterpret_cast<const uint4*>(a);
        pa1 = *reinterpret_cast<const uint4*>(a + rowskip);
        pb0 = *reinterpret_cast<const uint4*>(b);
        pb1 = *reinterpret_cast<const uint4*>(b + rowskip);
    };
    auto sstore = [&](int buf) {
        *reinterpret_cast<uint4*>(&sA[buf][r * SROW + c8 * 16])        = pa0;
        *reinterpret_cast<uint4*>(&sA[buf][(r + 64) * SROW + c8 * 16]) = pa1;
        *reinterpret_cast<uint4*>(&sB[buf][r * SROW + c8 * 16])        = pb0;
        *reinterpret_cast<uint4*>(&sB[buf][(r + 64) * SROW + c8 * 16]) = pb1;
    };

    float acc[4][4][4];
#pragma unroll
    for (int mi = 0; mi < 4; ++mi)
#pragma unroll
        for (int ni = 0; ni < 4; ++ni)
#pragma unroll
            for (int e = 0; e < 4; ++e) acc[mi][ni][e] = 0.f;

    gload(0);
    sstore(0);
    __syncthreads();

    const unsigned uA0 = (unsigned)__cvta_generic_to_shared(&sA[0][0]);
    const unsigned uB0 = (unsigned)__cvta_generic_to_shared(&sB[0][0]);
    const unsigned bufstride = 128 * SROW;

    // per-warp LDSM base offsets
    const unsigned aoff = (warp_m * 64 + (lane & 15)) * SROW + (lane >> 4) * 16;
    const unsigned boff = (warp_n * 32 + (lane & 7)) * SROW + ((lane >> 3) & 1) * 16;

    for (int c = 0; c < 16; ++c) {
        const int buf = c & 1;
        if (c < 15) gload(c + 1);

#pragma unroll
        for (int kk = 0; kk < 2; ++kk) {
            unsigned a[4][4], b[4][2];
#pragma unroll
            for (int mi = 0; mi < 4; ++mi)
                ldsm_x4(a[mi], uA0 + buf * bufstride + aoff + mi * 16 * SROW + kk * 32);
#pragma unroll
            for (int ni = 0; ni < 4; ++ni)
                ldsm_x2(b[ni], uB0 + buf * bufstride + boff + ni * 8 * SROW + kk * 32);
#pragma unroll
            for (int mi = 0; mi < 4; ++mi)
#pragma unroll
                for (int ni = 0; ni < 4; ++ni)
                    mma16816(acc[mi][ni], a[mi], b[ni]);
        }
        if (c < 15) sstore(buf ^ 1);
        __syncthreads();
    }

    // ---- fused epilogue: approx top-10 per (query row, 32-col warp tile) ----
    const int g    = lane >> 2;      // row group within 8
    const int qoff = lane & 3;
    const int tile32 = blockIdx.x * 4 + warp_n;
    const int cb   = col0 + warp_n * 32;

#pragma unroll
    for (int mi = 0; mi < 4; ++mi) {
#pragma unroll
        for (int h = 0; h < 2; ++h) {
            const int grow = row0 + warp_m * 64 + mi * 16 + g + 8 * h;
            unsigned long long k[8];
#pragma unroll
            for (int ni = 0; ni < 4; ++ni) {
#pragma unroll
                for (int j = 0; j < 2; ++j) {
                    int col = cb + ni * 8 + qoff * 2 + j;
                    float s = fmaf(-2.f, acc[mi][ni][2 * h + j], g_d2[col]);
                    k[ni * 2 + j] = (col < NDATA) ? pack_key(s, col) : ~0ull;
                }
            }
            unsigned long long* dst = g_part + ((size_t)grow * NT32 + tile32) * 10;
#pragma unroll
            for (int rr = 0; rr < 10; ++rr) {
                unsigned long long m = k[0];
#pragma unroll
                for (int j = 1; j < 8; ++j) m = u64min(m, k[j]);
                m = u64min(m, __shfl_xor_sync(0xffffffffu, m, 1));
                m = u64min(m, __shfl_xor_sync(0xffffffffu, m, 2));
                if (qoff == 0) dst[rr] = m;
#pragma unroll
                for (int j = 0; j < 8; ++j) if (k[j] == m) k[j] = ~0ull;
            }
        }
    }
}

// ---------------------------------------------------------------------------
// Kernel 4: merge 1564 sorted 10-lists -> top-64 candidate indices per query.
// 32 threads per query; smem double-buffered pairwise 64-merges.
// ---------------------------------------------------------------------------
__global__ __launch_bounds__(32) void merge_cand_kernel() {
    const int q   = blockIdx.x;
    const int tid = threadIdx.x;
    __shared__ unsigned long long S[2][32][65];

    unsigned long long* L = S[0][tid];
#pragma unroll
    for (int i = 0; i < 64; ++i) L[i] = ~0ull;

    const unsigned long long* part = g_part + (size_t)q * NT32 * 10;
    for (int t = tid; t < NT32; t += 32) {
        const unsigned long long* tl = part + t * 10;
#pragma unroll
        for (int s = 0; s < 10; ++s) {
            unsigned long long key = tl[s];
            if (key >= L[63]) break;            // list ascending -> done
            int p = 63;
            while (p > 0 && key < L[p - 1]) { L[p] = L[p - 1]; --p; }
            L[p] = key;
        }
    }
    __syncthreads();

    int cur = 0;
    for (int Lv = 16; Lv >= 1; Lv >>= 1) {
        if (tid < Lv) {
            const unsigned long long* A = S[cur][tid];
            const unsigned long long* B = S[cur][tid + Lv];
            unsigned long long* O = S[cur ^ 1][tid];
            int ia = 0, ib = 0;
            for (int i = 0; i < 64; ++i) {
                unsigned long long av = A[ia], bv = B[ib];
                if (av <= bv) { O[i] = av; ++ia; }
                else          { O[i] = bv; ++ib; }
            }
        }
        __syncthreads();
        cur ^= 1;
    }

    g_cand[q * 64 + tid]      = (int)(S[cur][0][tid] & 0xffffffffu);
    g_cand[q * 64 + tid + 32] = (int)(S[cur][0][tid + 32] & 0xffffffffu);
}

// ---------------------------------------------------------------------------
// Kernel 5: exact fp32 rescore of 64 candidates + top-10 + mode.
// One block (256 threads) per query.
// ---------------------------------------------------------------------------
__global__ __launch_bounds__(256) void rescore_kernel(const float* __restrict__ X,
                                                      const float* __restrict__ data,
                                                      const int* __restrict__ t32,
                                                      float* __restrict__ out) {
    const int q    = blockIdx.x;
    const int tid  = threadIdx.x;
    const int lane = tid & 31;
    const int wid  = tid >> 5;

    __shared__ float4 xq[128];                 // 512 floats
    __shared__ unsigned long long keys[64];

    if (tid < 128) xq[tid] = reinterpret_cast<const float4*>(X + (size_t)q * D)[tid];
    __syncthreads();

    for (int ci = wid; ci < 64; ci += 8) {
        const int c = g_cand[q * 64 + ci];
        const float4* drow = reinterpret_cast<const float4*>(data + (size_t)c * D);
        float dot = 0.f;
#pragma unroll
        for (int u = 0; u < 4; ++u) {
            float4 dv = drow[lane * 4 + u];
            float4 xv = xq[lane * 4 + u];
            dot += dv.x * xv.x + dv.y * xv.y + dv.z * xv.z + dv.w * xv.w;
        }
#pragma unroll
        for (int off = 16; off > 0; off >>= 1) dot += __shfl_down_sync(0xffffffffu, dot, off);
        if (lane == 0) keys[ci] = pack_key(fmaf(-2.f, dot, g_d2[c]), c);
    }
    __syncthreads();

    if (wid == 0) {
        unsigned long long k0 = keys[lane], k1 = keys[lane + 32];
        unsigned long long top[10];
#pragma unroll
        for (int rr = 0; rr < 10; ++rr) {
            unsigned long long m = u64min(k0, k1);
#pragma unroll
            for (int off = 16; off > 0; off >>= 1)
                m = u64min(m, __shfl_xor_sync(0xffffffffu, m, off));
            top[rr] = m;
            if (k0 == m) k0 = ~0ull;
            if (k1 == m) k1 = ~0ull;
        }
        if (lane == 0) {
            const int is64 = g_t_is_i64;
            int lab[10];
#pragma unroll
            for (int i = 0; i < 10; ++i) {
                int w = (int)(top[i] & 0xffffffffu);
                lab[i] = is64 ? t32[2 * w] : t32[w];
            }
            int bestLab = 0x7fffffff, bestCnt = 0;
#pragma unroll
            for (int i = 0; i < 10; ++i) {
                int c = 0;
#pragma unroll
                for (int j = 0; j < 10; ++j) c += (lab[j] == lab[i]) ? 1 : 0;
                if (c > bestCnt || (c == bestCnt && lab[i] < bestLab)) { bestCnt = c; bestLab = lab[i]; }
            }
            out[q] = (float)bestLab;
        }
    }
}

// ---------------------------------------------------------------------------
extern "C" void kernel_launch(void* const* d_in, const int* in_sizes, int n_in,
                              void* d_out, int out_size) {
    const float* X    = nullptr;
    const float* data = nullptr;
    const int*   t32  = nullptr;
    for (int i = 0; i < n_in; ++i) {
        if (in_sizes[i] == Q * D)            X    = (const float*)d_in[i];
        else if (in_sizes[i] == NDATA * D)   data = (const float*)d_in[i];
        else if (in_sizes[i] == NDATA)       t32  = (const int*)d_in[i];
    }
    float* out = (float*)d_out;
    (void)out_size;

    detect_dtype_kernel<<<1, 256>>>(t32);
    row_norms_kernel<<<(NPAD * 32 + 255) / 256, 256>>>(data);
    cvt_x_kernel<<<(Q * D / 4 + 255) / 256, 256>>>(X);
    cvt_d_kernel<<<(NPAD * D / 4 + 255) / 256, 256>>>(data);

    dim3 grid(NPAD / 128, Q / 128);   // 391 x 8
    mma_topk_kernel<<<grid, 256>>>();

    merge_cand_kernel<<<Q, 32>>>();
    rescore_kernel<<<Q, 256>>>(X, data, t32, out);
}

// round 9
// speedup vs baseline: 3.3333x; 2.6515x over previous
#include <cuda_runtime.h>
#include <cuda_bf16.h>
#include <float.h>
#include <stdint.h>

#define Q      1024
#define D      512
#define NDATA  50000
#define NPAD   50048    // 391 * 128
#define NTILES 391      // 128-col tiles
#define NCAND  32

// ---------------- device scratch (allocation-free rule) ----------------
__device__ __nv_bfloat16 g_xb[(size_t)Q * D];                  // 1 MB
__device__ __nv_bfloat16 g_db[(size_t)NPAD * D];               // 51 MB (pad rows = 0)
__device__ unsigned long long g_part[(size_t)Q * NTILES * 10]; // 32 MB
__device__ int   g_cand[(size_t)Q * NCAND];
__device__ float g_d2[NPAD];
__device__ int   g_t_is_i64;

typedef unsigned long long ull;

__device__ __forceinline__ ull pack_key(float v, int idx) {
    unsigned int b = __float_as_uint(v);
    b = (b & 0x80000000u) ? ~b : (b | 0x80000000u);   // monotone float -> uint
    return ((ull)b << 32) | (unsigned int)idx;
}
__device__ __forceinline__ ull u64min(ull a, ull b) { return a < b ? a : b; }

__device__ __forceinline__ uint32_t smem_u32(const void* p) {
    uint32_t a;
    asm("{ .reg .u64 t; cvta.to.shared.u64 t, %1; cvt.u32.u64 %0, t; }" : "=r"(a) : "l"(p));
    return a;
}
__device__ __forceinline__ void ldsm_x4(unsigned* r, unsigned addr) {
    asm volatile("ldmatrix.sync.aligned.m8n8.x4.shared.b16 {%0,%1,%2,%3}, [%4];"
                 : "=r"(r[0]), "=r"(r[1]), "=r"(r[2]), "=r"(r[3]) : "r"(addr));
}
__device__ __forceinline__ void ldsm_x2(unsigned* r, unsigned addr) {
    asm volatile("ldmatrix.sync.aligned.m8n8.x2.shared.b16 {%0,%1}, [%2];"
                 : "=r"(r[0]), "=r"(r[1]) : "r"(addr));
}
__device__ __forceinline__ void mma16816(float* c, const unsigned* a, const unsigned* b) {
    asm volatile("mma.sync.aligned.m16n8k16.row.col.f32.bf16.bf16.f32 "
                 "{%0,%1,%2,%3}, {%4,%5,%6,%7}, {%8,%9}, {%0,%1,%2,%3};"
                 : "+f"(c[0]), "+f"(c[1]), "+f"(c[2]), "+f"(c[3])
                 : "r"(a[0]), "r"(a[1]), "r"(a[2]), "r"(a[3]), "r"(b[0]), "r"(b[1]));
}
__device__ __forceinline__ void cp_async16(uint32_t dst, const void* src) {
    asm volatile("cp.async.cg.shared.global [%0], [%1], 16;" :: "r"(dst), "l"(src));
}
#define CP_COMMIT() asm volatile("cp.async.commit_group;" ::: "memory")
#define CP_WAIT(n)  asm volatile("cp.async.wait_group %0;" :: "n"(n) : "memory")

// ---------------------------------------------------------------------------
// Kernel 0: targets dtype detect (int64 LE -> all odd words zero)
// ---------------------------------------------------------------------------
__global__ __launch_bounds__(256) void detect_dtype_kernel(const int* __restrict__ t32) {
    __shared__ int any_nz;
    if (threadIdx.x == 0) any_nz = 0;
    __syncthreads();
    int local = 0;
    for (int i = threadIdx.x; i < NDATA; i += 256) local |= t32[2 * i + 1];
    if (local) atomicOr(&any_nz, 1);
    __syncthreads();
    if (threadIdx.x == 0) g_t_is_i64 = (any_nz == 0) ? 1 : 0;
}

// ---------------------------------------------------------------------------
// Kernel 1: per-row squared norms (fp32, exact), pad rows -> 0
// ---------------------------------------------------------------------------
__global__ __launch_bounds__(256) void row_norms_kernel(const float* __restrict__ data) {
    int gw   = (blockIdx.x * blockDim.x + threadIdx.x) >> 5;
    int lane = threadIdx.x & 31;
    if (gw >= NPAD) return;
    if (gw >= NDATA) { if (lane == 0) g_d2[gw] = 0.f; return; }
    const float4* row = reinterpret_cast<const float4*>(data + (size_t)gw * D);
    float s = 0.f;
#pragma unroll
    for (int j = 0; j < 4; ++j) {
        float4 v = row[lane + 32 * j];
        s += v.x * v.x + v.y * v.y + v.z * v.z + v.w * v.w;
    }
#pragma unroll
    for (int off = 16; off > 0; off >>= 1) s += __shfl_down_sync(0xffffffffu, s, off);
    if (lane == 0) g_d2[gw] = s;
}

// ---------------------------------------------------------------------------
// Kernel 2a/2b: fp32 -> bf16 conversion
// ---------------------------------------------------------------------------
__global__ __launch_bounds__(256) void cvt_x_kernel(const float* __restrict__ X) {
    int i4 = blockIdx.x * blockDim.x + threadIdx.x;
    if (i4 >= Q * D / 4) return;
    float4 v = reinterpret_cast<const float4*>(X)[i4];
    __nv_bfloat162* o = reinterpret_cast<__nv_bfloat162*>(g_xb);
    o[2 * i4]     = __floats2bfloat162_rn(v.x, v.y);
    o[2 * i4 + 1] = __floats2bfloat162_rn(v.z, v.w);
}
__global__ __launch_bounds__(256) void cvt_d_kernel(const float* __restrict__ data) {
    int i4 = blockIdx.x * blockDim.x + threadIdx.x;
    if (i4 >= NPAD * D / 4) return;
    __nv_bfloat162* o = reinterpret_cast<__nv_bfloat162*>(g_db);
    if (i4 < NDATA * D / 4) {
        float4 v = reinterpret_cast<const float4*>(data)[i4];
        o[2 * i4]     = __floats2bfloat162_rn(v.x, v.y);
        o[2 * i4 + 1] = __floats2bfloat162_rn(v.z, v.w);
    } else {
        o[2 * i4]     = __floats2bfloat162_rn(0.f, 0.f);
        o[2 * i4 + 1] = __floats2bfloat162_rn(0.f, 0.f);
    }
}

// ---------------------------------------------------------------------------
// Kernel 3: bf16 HMMA score GEMM (128x128 block, K=512) + fused per-128-tile
// exact-in-bf16 top-10 per query row.
//   8 warps: warp_m = wid&1 (64 rows), warp_n = wid>>1 (32 cols)
//   cp.async double-buffered smem, 16 chunks of K=32.
//   Epilogue: warp-level top-10 per 32-col subtile -> smem, 4-way merge -> g_part.
// ---------------------------------------------------------------------------
#define SROW 80          // bytes per smem row (32 bf16 = 64B + 16B pad)
#define BUFB (128 * SROW)  // 10240 B per tile buffer

struct Tiles { unsigned char A[2][BUFB]; unsigned char B[2][BUFB]; };
union SmemU {
    Tiles t;                    // 40 KB
    ull   lists[128][4][10];    // 40 KB (reused after MMA)
};

__global__ __launch_bounds__(256, 2) void mma_topk_kernel() {
    __shared__ SmemU su;
    __shared__ float sd2[128];

    const int tid    = threadIdx.x;
    const int lane   = tid & 31;
    const int wid    = tid >> 5;
    const int warp_m = wid & 1;
    const int warp_n = wid >> 1;
    const int row0   = blockIdx.y * 128;
    const int col0   = blockIdx.x * 128;

    const uint32_t uA = smem_u32(su.t.A[0]);
    const uint32_t uB = smem_u32(su.t.B[0]);

    if (tid < 128) sd2[tid] = g_d2[col0 + tid];

    // cp.async fill of one K=32 chunk into buffer `buf`
    auto fill = [&](int kc, int buf) {
#pragma unroll
        for (int i = 0; i < 4; ++i) {
            int idx = tid + i * 256;          // 0..1023
            int isB = idx >> 9;
            int e   = idx & 511;
            int r   = e >> 2;                 // 0..127
            int c16 = e & 3;                  // 16B unit within 64B row
            uint32_t dst = (isB ? uB : uA) + buf * BUFB + r * SROW + c16 * 16;
            const __nv_bfloat16* src = isB
                ? (g_db + (size_t)(col0 + r) * D + kc * 32 + c16 * 8)
                : (g_xb + (size_t)(row0 + r) * D + kc * 32 + c16 * 8);
            cp_async16(dst, src);
        }
        CP_COMMIT();
    };

    float acc[4][4][4];
#pragma unroll
    for (int mi = 0; mi < 4; ++mi)
#pragma unroll
        for (int ni = 0; ni < 4; ++ni)
#pragma unroll
            for (int e = 0; e < 4; ++e) acc[mi][ni][e] = 0.f;

    const unsigned aoff = (warp_m * 64 + (lane & 15)) * SROW + (lane >> 4) * 16;
    const unsigned boff = (warp_n * 32 + (lane & 7)) * SROW + ((lane >> 3) & 1) * 16;

    fill(0, 0);
    for (int c = 0; c < 16; ++c) {
        const int buf = c & 1;
        if (c < 15) fill(c + 1, buf ^ 1);
        if (c < 15) { CP_WAIT(1); } else { CP_WAIT(0); }
        __syncthreads();

#pragma unroll
        for (int kk = 0; kk < 2; ++kk) {
            unsigned a[4][4], b[4][2];
#pragma unroll
            for (int mi = 0; mi < 4; ++mi)
                ldsm_x4(a[mi], uA + buf * BUFB + aoff + mi * 16 * SROW + kk * 32);
#pragma unroll
            for (int ni = 0; ni < 4; ++ni)
                ldsm_x2(b[ni], uB + buf * BUFB + boff + ni * 8 * SROW + kk * 32);
#pragma unroll
            for (int mi = 0; mi < 4; ++mi)
#pragma unroll
                for (int ni = 0; ni < 4; ++ni)
                    mma16816(acc[mi][ni], a[mi], b[ni]);
        }
        __syncthreads();   // reads done before buffer refilled (next-next iter)
    }
    // tiles now dead; union reuse as `lists` is safe after the last sync above

    // ---- epilogue: warp-level top-10 per (row, 32-col subtile) -> smem ----
    const int g    = lane >> 2;      // row group within 8
    const int qoff = lane & 3;
    const int cb   = warp_n * 32;

#pragma unroll
    for (int mi = 0; mi < 4; ++mi) {
#pragma unroll
        for (int h = 0; h < 2; ++h) {
            const int lrow = warp_m * 64 + mi * 16 + g + 8 * h;
            ull k[8];
#pragma unroll
            for (int ni = 0; ni < 4; ++ni) {
#pragma unroll
                for (int j = 0; j < 2; ++j) {
                    int lcol = cb + ni * 8 + qoff * 2 + j;
                    int col  = col0 + lcol;
                    float s  = fmaf(-2.f, acc[mi][ni][2 * h + j], sd2[lcol]);
                    k[ni * 2 + j] = (col < NDATA) ? pack_key(s, col) : ~0ull;
                }
            }
#pragma unroll
            for (int rr = 0; rr < 10; ++rr) {
                ull m = k[0];
#pragma unroll
                for (int j = 1; j < 8; ++j) m = u64min(m, k[j]);
                m = u64min(m, __shfl_xor_sync(0xffffffffu, m, 1));
                m = u64min(m, __shfl_xor_sync(0xffffffffu, m, 2));
                if (qoff == 0) su.lists[lrow][warp_n][rr] = m;
#pragma unroll
                for (int j = 0; j < 8; ++j) if (k[j] == m) k[j] = ~0ull;
            }
        }
    }
    __syncthreads();

    // ---- per-row 4-way merge of sorted 10-lists -> g_part ----
    if (tid < 128) {
        const ull* L0 = su.lists[tid][0];
        const ull* L1 = su.lists[tid][1];
        const ull* L2 = su.lists[tid][2];
        const ull* L3 = su.lists[tid][3];
        int h0 = 0, h1 = 0, h2 = 0, h3 = 0;
        ull* dst = g_part + ((size_t)(row0 + tid) * NTILES + blockIdx.x) * 10;
#pragma unroll
        for (int i = 0; i < 10; ++i) {
            ull v0 = (h0 < 10) ? L0[h0] : ~0ull;
            ull v1 = (h1 < 10) ? L1[h1] : ~0ull;
            ull v2 = (h2 < 10) ? L2[h2] : ~0ull;
            ull v3 = (h3 < 10) ? L3[h3] : ~0ull;
            ull m01 = u64min(v0, v1), m23 = u64min(v2, v3);
            ull m = u64min(m01, m23);
            dst[i] = m;
            if (m == v0)      ++h0;
            else if (m == v1) ++h1;
            else if (m == v2) ++h2;
            else              ++h3;
        }
    }
}

// ---------------------------------------------------------------------------
// Kernel 4: merge 391 sorted 10-lists -> top-32 candidates per query.
// ---------------------------------------------------------------------------
__global__ __launch_bounds__(256) void merge_cand_kernel() {
    const int q   = blockIdx.x;
    const int tid = threadIdx.x;
    const ull* part = g_part + (size_t)q * NTILES * 10;

    ull L[NCAND];
#pragma unroll
    for (int i = 0; i < NCAND; ++i) L[i] = ~0ull;

    for (int t = tid; t < NTILES; t += 256) {
        const ull* tl = part + t * 10;
#pragma unroll
        for (int s = 0; s < 10; ++s) {
            ull key = tl[s];
            if (key >= L[NCAND - 1]) break;       // tile list ascending -> done
            L[NCAND - 1] = key;
#pragma unroll
            for (int p = NCAND - 1; p > 0; --p) {
                if (L[p] < L[p - 1]) { ull x = L[p]; L[p] = L[p - 1]; L[p - 1] = x; }
            }
        }
    }

    __shared__ ull sl[256][NCAND];
#pragma unroll
    for (int i = 0; i < NCAND; ++i) sl[tid][i] = L[i];
    __syncthreads();

    for (int Lv = 128; Lv >= 1; Lv >>= 1) {
        if (tid < Lv) {
            const ull* A = sl[tid];
            const ull* B = sl[tid + Lv];
            ull outm[NCAND];
            int ia = 0, ib = 0;
#pragma unroll
            for (int i = 0; i < NCAND; ++i) {
                ull av = A[ia], bv = B[ib];
                if (av <= bv) { outm[i] = av; ++ia; }
                else          { outm[i] = bv; ++ib; }
            }
#pragma unroll
            for (int i = 0; i < NCAND; ++i) sl[tid][i] = outm[i];
        }
        __syncthreads();
    }

    if (tid < NCAND) g_cand[q * NCAND + tid] = (int)(sl[0][tid] & 0xffffffffu);
}

// ---------------------------------------------------------------------------
// Kernel 5: exact fp32 rescore of 32 candidates + top-10 + mode.
// ---------------------------------------------------------------------------
__global__ __launch_bounds__(256) void rescore_kernel(const float* __restrict__ X,
                                                      const float* __restrict__ data,
                                                      const int* __restrict__ t32,
                                                      float* __restrict__ out) {
    const int q    = blockIdx.x;
    const int tid  = threadIdx.x;
    const int lane = tid & 31;
    const int wid  = tid >> 5;

    __shared__ float4 xq[128];
    __shared__ ull keys[NCAND];

    if (tid < 128) xq[tid] = reinterpret_cast<const float4*>(X + (size_t)q * D)[tid];
    __syncthreads();

#pragma unroll
    for (int rr = 0; rr < NCAND / 8; ++rr) {
        int ci = wid + rr * 8;
        const int c = g_cand[q * NCAND + ci];
        const float4* drow = reinterpret_cast<const float4*>(data + (size_t)c * D);
        float dot = 0.f;
#pragma unroll
        for (int u = 0; u < 4; ++u) {
            float4 dv = drow[lane * 4 + u];
            float4 xv = xq[lane * 4 + u];
            dot += dv.x * xv.x + dv.y * xv.y + dv.z * xv.z + dv.w * xv.w;
        }
#pragma unroll
        for (int off = 16; off > 0; off >>= 1) dot += __shfl_down_sync(0xffffffffu, dot, off);
        if (lane == 0) keys[ci] = pack_key(fmaf(-2.f, dot, g_d2[c]), c);
    }
    __syncthreads();

    if (wid == 0) {
        ull k0 = keys[lane];               // NCAND == 32
        ull top[10];
#pragma unroll
        for (int rr = 0; rr < 10; ++rr) {
            ull m = k0;
#pragma unroll
            for (int off = 16; off > 0; off >>= 1)
                m = u64min(m, __shfl_xor_sync(0xffffffffu, m, off));
            top[rr] = m;
            if (k0 == m) k0 = ~0ull;
        }
        if (lane == 0) {
            const int is64 = g_t_is_i64;
            int lab[10];
#pragma unroll
            for (int i = 0; i < 10; ++i) {
                int w = (int)(top[i] & 0xffffffffu);
                lab[i] = is64 ? t32[2 * w] : t32[w];
            }
            int bestLab = 0x7fffffff, bestCnt = 0;
#pragma unroll
            for (int i = 0; i < 10; ++i) {
                int c = 0;
#pragma unroll
                for (int j = 0; j < 10; ++j) c += (lab[j] == lab[i]) ? 1 : 0;
                if (c > bestCnt || (c == bestCnt && lab[i] < bestLab)) { bestCnt = c; bestLab = lab[i]; }
            }
            out[q] = (float)bestLab;
        }
    }
}

// ---------------------------------------------------------------------------
extern "C" void kernel_launch(void* const* d_in, const int* in_sizes, int n_in,
                              void* d_out, int out_size) {
    const float* X    = nullptr;
    const float* data = nullptr;
    const int*   t32  = nullptr;
    for (int i = 0; i < n_in; ++i) {
        if (in_sizes[i] == Q * D)            X    = (const float*)d_in[i];
        else if (in_sizes[i] == NDATA * D)   data = (const float*)d_in[i];
        else if (in_sizes[i] == NDATA)       t32  = (const int*)d_in[i];
    }
    float* out = (float*)d_out;
    (void)out_size;

    detect_dtype_kernel<<<1, 256>>>(t32);
    row_norms_kernel<<<(NPAD * 32 + 255) / 256, 256>>>(data);
    cvt_x_kernel<<<(Q * D / 4 + 255) / 256, 256>>>(X);
    cvt_d_kernel<<<(NPAD * D / 4 + 255) / 256, 256>>>(data);

    dim3 grid(NTILES, Q / 128);   // 391 x 8
    mma_topk_kernel<<<grid, 256>>>();

    merge_cand_kernel<<<Q, 256>>>();
    rescore_kernel<<<Q, 256>>>(X, data, t32, out);
}

// round 12
// speedup vs baseline: 3.5530x; 1.0659x over previous
#include <cuda_runtime.h>
#include <cuda_bf16.h>
#include <float.h>
#include <stdint.h>

#define Q      1024
#define D      512
#define NDATA  50000
#define NPAD   50048    // 391 * 128
#define NTILES 391      // 128-col tiles
#define NCAND  32

// ---------------- device scratch (allocation-free rule) ----------------
__device__ __nv_bfloat16 g_xb[(size_t)Q * D];                  // 1 MB
__device__ __nv_bfloat16 g_db[(size_t)NPAD * D];               // 51 MB (pad rows = 0)
__device__ unsigned long long g_part[(size_t)Q * NTILES * 10]; // 32 MB
__device__ int   g_cand[(size_t)Q * NCAND];
__device__ float g_d2[NPAD];
__device__ int   g_t_is_i64;

typedef unsigned long long ull;

__device__ __forceinline__ ull pack_key(float v, int idx) {
    unsigned int b = __float_as_uint(v);
    b = (b & 0x80000000u) ? ~b : (b | 0x80000000u);   // monotone float -> uint
    return ((ull)b << 32) | (unsigned int)idx;
}
__device__ __forceinline__ ull u64min(ull a, ull b) { return a < b ? a : b; }

__device__ __forceinline__ uint32_t smem_u32(const void* p) {
    uint32_t a;
    asm("{ .reg .u64 t; cvta.to.shared.u64 t, %1; cvt.u32.u64 %0, t; }" : "=r"(a) : "l"(p));
    return a;
}
__device__ __forceinline__ void ldsm_x4(unsigned* r, unsigned addr) {
    asm volatile("ldmatrix.sync.aligned.m8n8.x4.shared.b16 {%0,%1,%2,%3}, [%4];"
                 : "=r"(r[0]), "=r"(r[1]), "=r"(r[2]), "=r"(r[3]) : "r"(addr));
}
__device__ __forceinline__ void ldsm_x2(unsigned* r, unsigned addr) {
    asm volatile("ldmatrix.sync.aligned.m8n8.x2.shared.b16 {%0,%1}, [%2];"
                 : "=r"(r[0]), "=r"(r[1]) : "r"(addr));
}
__device__ __forceinline__ void mma16816(float* c, const unsigned* a, const unsigned* b) {
    asm volatile("mma.sync.aligned.m16n8k16.row.col.f32.bf16.bf16.f32 "
                 "{%0,%1,%2,%3}, {%4,%5,%6,%7}, {%8,%9}, {%0,%1,%2,%3};"
                 : "+f"(c[0]), "+f"(c[1]), "+f"(c[2]), "+f"(c[3])
                 : "r"(a[0]), "r"(a[1]), "r"(a[2]), "r"(a[3]), "r"(b[0]), "r"(b[1]));
}
__device__ __forceinline__ void cp_async16(uint32_t dst, const void* src) {
    asm volatile("cp.async.cg.shared.global [%0], [%1], 16;" :: "r"(dst), "l"(src));
}
#define CP_COMMIT() asm volatile("cp.async.commit_group;" ::: "memory")
#define CP_WAIT(n)  asm volatile("cp.async.wait_group %0;" :: "n"(n) : "memory")

// ---------------------------------------------------------------------------
// Kernel 0: targets dtype detect (int64 LE -> all odd words zero)
// ---------------------------------------------------------------------------
__global__ __launch_bounds__(256) void detect_dtype_kernel(const int* __restrict__ t32) {
    __shared__ int any_nz;
    if (threadIdx.x == 0) any_nz = 0;
    __syncthreads();
    int local = 0;
    for (int i = threadIdx.x; i < NDATA; i += 256) local |= t32[2 * i + 1];
    if (local) atomicOr(&any_nz, 1);
    __syncthreads();
    if (threadIdx.x == 0) g_t_is_i64 = (any_nz == 0) ? 1 : 0;
}

// ---------------------------------------------------------------------------
// Kernel 1 (fused): per-row norms (fp32) + fp32->bf16 data conversion.
// One warp per data row; data read ONCE. Pad rows: zeros.
// ---------------------------------------------------------------------------
__global__ __launch_bounds__(256) void norms_cvt_kernel(const float* __restrict__ data) {
    int gw   = (blockIdx.x * blockDim.x + threadIdx.x) >> 5;
    int lane = threadIdx.x & 31;
    if (gw >= NPAD) return;
    __nv_bfloat162* orow = reinterpret_cast<__nv_bfloat162*>(g_db + (size_t)gw * D);
    if (gw >= NDATA) {
        if (lane == 0) g_d2[gw] = 0.f;
        __nv_bfloat162 z = __floats2bfloat162_rn(0.f, 0.f);
#pragma unroll
        for (int j = 0; j < 4; ++j) {
            int e = lane + 32 * j;
            orow[2 * e] = z; orow[2 * e + 1] = z;
        }
        return;
    }
    const float4* row = reinterpret_cast<const float4*>(data + (size_t)gw * D);
    float s = 0.f;
#pragma unroll
    for (int j = 0; j < 4; ++j) {
        int e = lane + 32 * j;
        float4 v = row[e];
        s += v.x * v.x + v.y * v.y + v.z * v.z + v.w * v.w;
        orow[2 * e]     = __floats2bfloat162_rn(v.x, v.y);
        orow[2 * e + 1] = __floats2bfloat162_rn(v.z, v.w);
    }
#pragma unroll
    for (int off = 16; off > 0; off >>= 1) s += __shfl_down_sync(0xffffffffu, s, off);
    if (lane == 0) g_d2[gw] = s;
}

// ---------------------------------------------------------------------------
// Kernel 2: fp32 -> bf16 conversion of X
// ---------------------------------------------------------------------------
__global__ __launch_bounds__(256) void cvt_x_kernel(const float* __restrict__ X) {
    int i4 = blockIdx.x * blockDim.x + threadIdx.x;
    if (i4 >= Q * D / 4) return;
    float4 v = reinterpret_cast<const float4*>(X)[i4];
    __nv_bfloat162* o = reinterpret_cast<__nv_bfloat162*>(g_xb);
    o[2 * i4]     = __floats2bfloat162_rn(v.x, v.y);
    o[2 * i4 + 1] = __floats2bfloat162_rn(v.z, v.w);
}

// ---------------------------------------------------------------------------
// Kernel 3: bf16 HMMA score GEMM (128x128 block, K=512) + fused per-128-tile
// exact-in-bf16 top-10 per query row.
//   3-stage cp.async pipeline (dynamic smem, 60 KB), ONE sync per K=32 chunk.
//   8 warps: warp_m = wid&1 (64 rows), warp_n = wid>>1 (32 cols).
//   Epilogue: warp top-10 per 32-col subtile -> smem, 4-way merge -> g_part.
// ---------------------------------------------------------------------------
#define SROW   80                 // bytes per smem row (32 bf16 = 64B + 16B pad)
#define TILEB  (128 * SROW)       // 10240 B per tensor per stage
#define STAGEB (2 * TILEB)        // A + B
#define NSTAGE 3
#define DYN_SMEM (NSTAGE * STAGEB)  // 61440 B

extern __shared__ unsigned char dynsmem[];

__global__ __launch_bounds__(256, 2) void mma_topk_kernel() {
    __shared__ float sd2[128];

    const int tid    = threadIdx.x;
    const int lane   = tid & 31;
    const int wid    = tid >> 5;
    const int warp_m = wid & 1;
    const int warp_n = wid >> 1;
    const int row0   = blockIdx.y * 128;
    const int col0   = blockIdx.x * 128;

    const uint32_t uS = smem_u32(dynsmem);

    if (tid < 128) sd2[tid] = g_d2[col0 + tid];

    // cp.async fill of one K=32 chunk into stage s
    auto fill = [&](int kc, int s) {
        const uint32_t uA = uS + s * STAGEB;
        const uint32_t uB = uA + TILEB;
#pragma unroll
        for (int i = 0; i < 4; ++i) {
            int idx = tid + i * 256;          // 0..1023
            int isB = idx >> 9;
            int e   = idx & 511;
            int r   = e >> 2;                 // 0..127
            int c16 = e & 3;                  // 16B unit within 64B row
            uint32_t dst = (isB ? uB : uA) + r * SROW + c16 * 16;
            const __nv_bfloat16* src = isB
                ? (g_db + (size_t)(col0 + r) * D + kc * 32 + c16 * 8)
                : (g_xb + (size_t)(row0 + r) * D + kc * 32 + c16 * 8);
            cp_async16(dst, src);
        }
        CP_COMMIT();
    };

    float acc[4][4][4];
#pragma unroll
    for (int mi = 0; mi < 4; ++mi)
#pragma unroll
        for (int ni = 0; ni < 4; ++ni)
#pragma unroll
            for (int e = 0; e < 4; ++e) acc[mi][ni][e] = 0.f;

    const unsigned aoff = (warp_m * 64 + (lane & 15)) * SROW + (lane >> 4) * 16;
    const unsigned boff = (warp_n * 32 + (lane & 7)) * SROW + ((lane >> 3) & 1) * 16;

    fill(0, 0);
    fill(1, 1);
    for (int c = 0; c < 16; ++c) {
        const int s = c % NSTAGE;
        if (c < 15) { CP_WAIT(1); } else { CP_WAIT(0); }   // fill(c) complete
        __syncthreads();                                    // all warps see stage s

        const uint32_t uA = uS + s * STAGEB;
        const uint32_t uB = uA + TILEB;
#pragma unroll
        for (int kk = 0; kk < 2; ++kk) {
            unsigned a[4][4], b[4][2];
#pragma unroll
            for (int mi = 0; mi < 4; ++mi)
                ldsm_x4(a[mi], uA + aoff + mi * 16 * SROW + kk * 32);
#pragma unroll
            for (int ni = 0; ni < 4; ++ni)
                ldsm_x2(b[ni], uB + boff + ni * 8 * SROW + kk * 32);
#pragma unroll
            for (int mi = 0; mi < 4; ++mi)
#pragma unroll
                for (int ni = 0; ni < 4; ++ni)
                    mma16816(acc[mi][ni], a[mi], b[ni]);
        }
        // stage (c+2)%3 was last read in compute(c-1); every warp passed the
        // sync above only after finishing compute(c-1) -> safe to overwrite.
        if (c + 2 < 16) fill(c + 2, (c + 2) % NSTAGE);
    }
    __syncthreads();   // all compute done; reuse dynsmem as merge lists

    ull (*lists)[4][10] = reinterpret_cast<ull (*)[4][10]>(dynsmem);   // 40 KB

    // ---- epilogue: warp-level top-10 per (row, 32-col subtile) -> smem ----
    const int g    = lane >> 2;      // row group within 8
    const int qoff = lane & 3;
    const int cb   = warp_n * 32;

#pragma unroll
    for (int mi = 0; mi < 4; ++mi) {
#pragma unroll
        for (int h = 0; h < 2; ++h) {
            const int lrow = warp_m * 64 + mi * 16 + g + 8 * h;
            ull k[8];
#pragma unroll
            for (int ni = 0; ni < 4; ++ni) {
#pragma unroll
                for (int j = 0; j < 2; ++j) {
                    int lcol = cb + ni * 8 + qoff * 2 + j;
                    int col  = col0 + lcol;
                    float s  = fmaf(-2.f, acc[mi][ni][2 * h + j], sd2[lcol]);
                    k[ni * 2 + j] = (col < NDATA) ? pack_key(s, col) : ~0ull;
                }
            }
#pragma unroll
            for (int rr = 0; rr < 10; ++rr) {
                ull m = k[0];
#pragma unroll
                for (int j = 1; j < 8; ++j) m = u64min(m, k[j]);
                m = u64min(m, __shfl_xor_sync(0xffffffffu, m, 1));
                m = u64min(m, __shfl_xor_sync(0xffffffffu, m, 2));
                if (qoff == 0) lists[lrow][warp_n][rr] = m;
#pragma unroll
                for (int j = 0; j < 8; ++j) if (k[j] == m) k[j] = ~0ull;
            }
        }
    }
    __syncthreads();

    // ---- per-row 4-way merge of sorted 10-lists -> g_part ----
    if (tid < 128) {
        const ull* L0 = lists[tid][0];
        const ull* L1 = lists[tid][1];
        const ull* L2 = lists[tid][2];
        const ull* L3 = lists[tid][3];
        int h0 = 0, h1 = 0, h2 = 0, h3 = 0;
        ull* dst = g_part + ((size_t)(row0 + tid) * NTILES + blockIdx.x) * 10;
#pragma unroll
        for (int i = 0; i < 10; ++i) {
            ull v0 = (h0 < 10) ? L0[h0] : ~0ull;
            ull v1 = (h1 < 10) ? L1[h1] : ~0ull;
            ull v2 = (h2 < 10) ? L2[h2] : ~0ull;
            ull v3 = (h3 < 10) ? L3[h3] : ~0ull;
            ull m01 = u64min(v0, v1), m23 = u64min(v2, v3);
            ull m = u64min(m01, m23);
            dst[i] = m;
            if (m == v0)      ++h0;
            else if (m == v1) ++h1;
            else if (m == v2) ++h2;
            else              ++h3;
        }
    }
}

// ---------------------------------------------------------------------------
// Kernel 4: merge 391 sorted 10-lists -> top-32 candidates per query.
// ---------------------------------------------------------------------------
__global__ __launch_bounds__(256) void merge_cand_kernel() {
    const int q   = blockIdx.x;
    const int tid = threadIdx.x;
    const ull* part = g_part + (size_t)q * NTILES * 10;

    ull L[NCAND];
#pragma unroll
    for (int i = 0; i < NCAND; ++i) L[i] = ~0ull;

    for (int t = tid; t < NTILES; t += 256) {
        const ull* tl = part + t * 10;
#pragma unroll
        for (int s = 0; s < 10; ++s) {
            ull key = tl[s];
            if (key >= L[NCAND - 1]) break;       // tile list ascending -> done
            L[NCAND - 1] = key;
#pragma unroll
            for (int p = NCAND - 1; p > 0; --p) {
                if (L[p] < L[p - 1]) { ull x = L[p]; L[p] = L[p - 1]; L[p - 1] = x; }
            }
        }
    }

    __shared__ ull sl[256][NCAND];
#pragma unroll
    for (int i = 0; i < NCAND; ++i) sl[tid][i] = L[i];
    __syncthreads();

    for (int Lv = 128; Lv >= 1; Lv >>= 1) {
        if (tid < Lv) {
            const ull* A = sl[tid];
            const ull* B = sl[tid + Lv];
            ull outm[NCAND];
            int ia = 0, ib = 0;
#pragma unroll
            for (int i = 0; i < NCAND; ++i) {
                ull av = A[ia], bv = B[ib];
                if (av <= bv) { outm[i] = av; ++ia; }
                else          { outm[i] = bv; ++ib; }
            }
#pragma unroll
            for (int i = 0; i < NCAND; ++i) sl[tid][i] = outm[i];
        }
        __syncthreads();
    }

    if (tid < NCAND) g_cand[q * NCAND + tid] = (int)(sl[0][tid] & 0xffffffffu);
}

// ---------------------------------------------------------------------------
// Kernel 5: exact fp32 rescore of 32 candidates + top-10 + mode.
// ---------------------------------------------------------------------------
__global__ __launch_bounds__(256) void rescore_kernel(const float* __restrict__ X,
                                                      const float* __restrict__ data,
                                                      const int* __restrict__ t32,
                                                      float* __restrict__ out) {
    const int q    = blockIdx.x;
    const int tid  = threadIdx.x;
    const int lane = tid & 31;
    const int wid  = tid >> 5;

    __shared__ float4 xq[128];
    __shared__ ull keys[NCAND];

    if (tid < 128) xq[tid] = reinterpret_cast<const float4*>(X + (size_t)q * D)[tid];
    __syncthreads();

#pragma unroll
    for (int rr = 0; rr < NCAND / 8; ++rr) {
        int ci = wid + rr * 8;
        const int c = g_cand[q * NCAND + ci];
        const float4* drow = reinterpret_cast<const float4*>(data + (size_t)c * D);
        float dot = 0.f;
#pragma unroll
        for (int u = 0; u < 4; ++u) {
            float4 dv = drow[lane * 4 + u];
            float4 xv = xq[lane * 4 + u];
            dot += dv.x * xv.x + dv.y * xv.y + dv.z * xv.z + dv.w * xv.w;
        }
#pragma unroll
        for (int off = 16; off > 0; off >>= 1) dot += __shfl_down_sync(0xffffffffu, dot, off);
        if (lane == 0) keys[ci] = pack_key(fmaf(-2.f, dot, g_d2[c]), c);
    }
    __syncthreads();

    if (wid == 0) {
        ull k0 = keys[lane];               // NCAND == 32
        ull top[10];
#pragma unroll
        for (int rr = 0; rr < 10; ++rr) {
            ull m = k0;
#pragma unroll
            for (int off = 16; off > 0; off >>= 1)
                m = u64min(m, __shfl_xor_sync(0xffffffffu, m, off));
            top[rr] = m;
            if (k0 == m) k0 = ~0ull;
        }
        if (lane == 0) {
            const int is64 = g_t_is_i64;
            int lab[10];
#pragma unroll
            for (int i = 0; i < 10; ++i) {
                int w = (int)(top[i] & 0xffffffffu);
                lab[i] = is64 ? t32[2 * w] : t32[w];
            }
            int bestLab = 0x7fffffff, bestCnt = 0;
#pragma unroll
            for (int i = 0; i < 10; ++i) {
                int c = 0;
#pragma unroll
                for (int j = 0; j < 10; ++j) c += (lab[j] == lab[i]) ? 1 : 0;
                if (c > bestCnt || (c == bestCnt && lab[i] < bestLab)) { bestCnt = c; bestLab = lab[i]; }
            }
            out[q] = (float)bestLab;
        }
    }
}

// ---------------------------------------------------------------------------
extern "C" void kernel_launch(void* const* d_in, const int* in_sizes, int n_in,
                              void* d_out, int out_size) {
    const float* X    = nullptr;
    const float* data = nullptr;
    const int*   t32  = nullptr;
    for (int i = 0; i < n_in; ++i) {
        if (in_sizes[i] == Q * D)            X    = (const float*)d_in[i];
        else if (in_sizes[i] == NDATA * D)   data = (const float*)d_in[i];
        else if (in_sizes[i] == NDATA)       t32  = (const int*)d_in[i];
    }
    float* out = (float*)d_out;
    (void)out_size;

    cudaFuncSetAttribute(mma_topk_kernel,
                         cudaFuncAttributeMaxDynamicSharedMemorySize, DYN_SMEM);

    detect_dtype_kernel<<<1, 256>>>(t32);
    norms_cvt_kernel<<<(NPAD * 32 + 255) / 256, 256>>>(data);
    cvt_x_kernel<<<(Q * D / 4 + 255) / 256, 256>>>(X);

    dim3 grid(NTILES, Q / 128);   // 391 x 8
    mma_topk_kernel<<<grid, 256, DYN_SMEM>>>();

    merge_cand_kernel<<<Q, 256>>>();
    rescore_kernel<<<Q, 256>>>(X, data, t32, out);
}